// round 13
// baseline (speedup 1.0000x reference)
#include <cuda_runtime.h>

// ---------------------------------------------------------------------------
// voxelization: 3 scales (2, 4, 1), spatial_shape (480, 360, 32), batch 8
// Output is ONE float32 buffer; per scale s (stride 18,000,001 f32):
//   [0, 8M)  bxyz (N x 4) | [8M, 10M) inv (N) | [10M, 18M) coors | [18M] num
// OUTSTRIDE is odd -> only 32-bit stores into out.
// FP model of the reference (XLA:CPU, default flags) - verified exact for
// scales 2 and 4 in round 12:
//   r2  = fl(fl(x*x) + fl(y*y))           (no contraction)
//   rho = IEEE sqrt(r2)
//   phi = glibc scalar fdlibm atan2f       (strict, no fp contraction)
//   bin = floor(((clip(v)-lo) * fl(1/crop)) * cells)
// ---------------------------------------------------------------------------

#define NPTS 2000000
#define OUTSTRIDE 18000001ll

#define W0 173056
#define W1 22528
#define W2 1382400
#define WOFF0 0
#define WOFF1 173056
#define WOFF2 195584
#define TOTW 1577984
#define B0 169
#define B1 22
#define B2 1350
#define BOFF0 0
#define BOFF1 2048
#define BOFF2 4096

static __device__ unsigned g_bitmap[TOTW];
static __device__ unsigned g_wpre[TOTW];
static __device__ int g_keys[3 * NPTS];
static __device__ int g_bsum[6144];
static __device__ int g_num[3];

// ---------------------------------------------------------------------------
// Bit-exact replica of glibc sysdeps/ieee754/flt-32 (Sun fdlibm) atanf/atan2f,
// strict FP (no contraction): every mul/add separately rounded.
// ---------------------------------------------------------------------------
__device__ __forceinline__ float fdl_atanf(float xin) {
    unsigned hx = __float_as_uint(xin);
    unsigned ix = hx & 0x7fffffffu;
    float x = xin;
    int id;
    if (ix >= 0x4c800000u) {  // |x| >= 2^26
        if (ix > 0x7f800000u) return __fadd_rn(xin, xin);
        float r = __fadd_rn(__uint_as_float(0x3fc90fdau), __uint_as_float(0x33a22168u));
        return (hx >> 31) ? -r : r;
    }
    if (ix < 0x3ee00000u) {       // |x| < 0.4375
        if (ix < 0x39800000u) return xin;  // |x| < 2^-12
        id = -1;
    } else {
        x = fabsf(x);
        if (ix < 0x3f980000u) {   // |x| < 1.1875
            if (ix < 0x3f300000u) {  // [0.4375, 0.6875)
                id = 0;
                x = __fdiv_rn(__fsub_rn(__fmul_rn(2.0f, x), 1.0f), __fadd_rn(2.0f, x));
            } else {                 // [0.6875, 1.1875)
                id = 1;
                x = __fdiv_rn(__fsub_rn(x, 1.0f), __fadd_rn(x, 1.0f));
            }
        } else {
            if (ix < 0x401c0000u) {  // [1.1875, 2.4375)
                id = 2;
                x = __fdiv_rn(__fsub_rn(x, 1.5f), __fadd_rn(1.0f, __fmul_rn(1.5f, x)));
            } else {                 // [2.4375, 2^26)
                id = 3;
                x = __fdiv_rn(-1.0f, x);
            }
        }
    }
    float z = __fmul_rn(x, x);
    float w = __fmul_rn(z, z);
    const float a0 = (float)3.33333333333329318027e-01;
    const float a1 = (float)-1.99999999998764832476e-01;
    const float a2 = (float)1.42857142725034663711e-01;
    const float a3 = (float)-1.11111104054623557880e-01;
    const float a4 = (float)9.09088713343650656196e-02;
    const float a5 = (float)-7.69187620504482999495e-02;
    const float a6 = (float)6.66107313738753120669e-02;
    const float a7 = (float)-5.83357013379057348645e-02;
    const float a8 = (float)4.97687799461593236017e-02;
    const float a9 = (float)-3.65315727442169155270e-02;
    const float a10 = (float)1.62858201153657823623e-02;
    float s1 = __fmul_rn(w, a10);
    s1 = __fadd_rn(a8, s1);
    s1 = __fmul_rn(w, s1);
    s1 = __fadd_rn(a6, s1);
    s1 = __fmul_rn(w, s1);
    s1 = __fadd_rn(a4, s1);
    s1 = __fmul_rn(w, s1);
    s1 = __fadd_rn(a2, s1);
    s1 = __fmul_rn(w, s1);
    s1 = __fadd_rn(a0, s1);
    s1 = __fmul_rn(z, s1);
    float s2 = __fmul_rn(w, a9);
    s2 = __fadd_rn(a7, s2);
    s2 = __fmul_rn(w, s2);
    s2 = __fadd_rn(a5, s2);
    s2 = __fmul_rn(w, s2);
    s2 = __fadd_rn(a3, s2);
    s2 = __fmul_rn(w, s2);
    s2 = __fadd_rn(a1, s2);
    s2 = __fmul_rn(w, s2);
    float s = __fadd_rn(s1, s2);
    if (id < 0) return __fsub_rn(x, __fmul_rn(x, s));
    float hi = __uint_as_float(id == 0 ? 0x3eed6338u : id == 1 ? 0x3f490fdau
                               : id == 2 ? 0x3f7b985eu : 0x3fc90fdau);
    float lo = __uint_as_float(id == 0 ? 0x31ac3769u : id == 1 ? 0x33222168u
                               : id == 2 ? 0x33140fb4u : 0x33a22168u);
    float t1 = __fsub_rn(__fmul_rn(x, s), lo);
    float zr = __fsub_rn(hi, __fsub_rn(t1, x));
    return (hx >> 31) ? -zr : zr;
}

__device__ __forceinline__ float fdl_atan2f(float y, float x) {
    unsigned hx = __float_as_uint(x), ix = hx & 0x7fffffffu;
    unsigned hy = __float_as_uint(y), iy = hy & 0x7fffffffu;
    const float pi = __uint_as_float(0x40490fdbu);
    const float pi_lo = __uint_as_float(0xb3bbbd2eu);
    const float pi_o_2 = __uint_as_float(0x3fc90fdbu);
    if (ix > 0x7f800000u || iy > 0x7f800000u) return __fadd_rn(x, y);
    if (hx == 0x3f800000u) return fdl_atanf(y);
    unsigned m = ((hy >> 31) & 1u) | ((hx >> 30) & 2u);
    if (iy == 0u) {
        switch (m) { case 0: case 1: return y; case 2: return pi; default: return -pi; }
    }
    if (ix == 0u) return (hy >> 31) ? -pi_o_2 : pi_o_2;
    if (ix == 0x7f800000u) {
        if (iy == 0x7f800000u) {
            float q = __fmul_rn(pi_o_2, 0.5f);
            switch (m) { case 0: return q; case 1: return -q;
                         case 2: return __fmul_rn(3.0f, q); default: return -__fmul_rn(3.0f, q); }
        } else {
            switch (m) { case 0: return 0.0f; case 1: return -0.0f;
                         case 2: return pi; default: return -pi; }
        }
    }
    if (iy == 0x7f800000u) return (hy >> 31) ? -pi_o_2 : pi_o_2;
    int k = ((int)iy - (int)ix) >> 23;
    float z;
    if (k > 26) {
        z = __fadd_rn(pi_o_2, __fmul_rn(0.5f, pi_lo));
        m &= 1u;
    } else if ((hx >> 31) && k < -26) {
        z = 0.0f;
    } else {
        z = fdl_atanf(fabsf(__fdiv_rn(y, x)));
    }
    switch (m) {
        case 0: return z;
        case 1: return -z;
        case 2: return __fsub_rn(pi, __fsub_rn(z, pi_lo));
        default: return __fsub_rn(__fsub_rn(z, pi_lo), pi);
    }
}

// bin = floor(((clip(v)-lo) * invcrop) * cells); invcrop = fl(1/crop)
__device__ __forceinline__ int gidx_r(float v, float lo, float hi,
                                      float invcrop, float cells) {
    float c = fminf(fmaxf(v, lo), hi);
    float t = __fsub_rn(c, lo);
    float u = __fmul_rn(t, invcrop);
    float g = __fmul_rn(u, cells);
    return (int)floorf(g);
}

__global__ __launch_bounds__(256) void k_clear() {
    int i = blockIdx.x * blockDim.x + threadIdx.x;
    uint4* p = (uint4*)g_bitmap;
    if (i < TOTW / 4) p[i] = make_uint4(0, 0, 0, 0);
}

__global__ __launch_bounds__(256) void k_points(const float4* __restrict__ pts,
                                                const int* __restrict__ batch,
                                                float* __restrict__ out) {
    int i = blockIdx.x * blockDim.x + threadIdx.x;
    if (i >= NPTS) return;
    float4 p = pts[i];
    int b = batch[i];
    float r2 = __fadd_rn(__fmul_rn(p.x, p.x), __fmul_rn(p.y, p.y));
    float rho = __fsqrt_rn(r2);
    float phi = fdl_atan2f(p.y, p.x);
    const float PI = 3.14159265358979323846f;
    const float TWO_PI = __fadd_rn(PI, PI);
    const int D0[3] = {240, 120, 480};
    const int D1[3] = {180, 90, 360};
    const int D2[3] = {16, 8, 32};
    const float CX[3] = {239.f, 119.f, 479.f};
    const float CY[3] = {179.f, 89.f, 359.f};
    const float CZ[3] = {15.f, 7.f, 31.f};
    const int WF[3] = {WOFF0, WOFF1, WOFF2};
    const float INV_X = __fdiv_rn(1.0f, 50.0f);
    const float INV_Y = __fdiv_rn(1.0f, TWO_PI);
    const float INV_Z = __fdiv_rn(1.0f, 6.0f);
    float bf = (float)b;
#pragma unroll
    for (int s = 0; s < 3; s++) {
        int gx = gidx_r(rho, 0.f, 50.f, INV_X, CX[s]);
        int gy = gidx_r(phi, -PI, PI, INV_Y, CY[s]);
        int gz = gidx_r(p.z, -4.f, 2.f, INV_Z, CZ[s]);
        int key = ((b * D0[s] + gx) * D1[s] + gy) * D2[s] + gz;
        g_keys[s * NPTS + i] = key;
        atomicOr(&g_bitmap[WF[s] + (key >> 5)], 1u << (key & 31));
        float* row = out + (long long)s * OUTSTRIDE + 4ll * i;
        row[0] = bf;
        row[1] = (float)gx;
        row[2] = (float)gy;
        row[3] = (float)gz;
    }
}

__global__ __launch_bounds__(256) void k_scanA(int woff, int boff) {
    int t = threadIdx.x, blk = blockIdx.x;
    const uint4* bm = (const uint4*)(g_bitmap + woff);
    uint4 w = bm[blk * 256 + t];
    int s = __popc(w.x) + __popc(w.y) + __popc(w.z) + __popc(w.w);
    for (int o = 16; o; o >>= 1) s += __shfl_down_sync(0xffffffffu, s, o);
    __shared__ int ws[8];
    if ((t & 31) == 0) ws[t >> 5] = s;
    __syncthreads();
    if (t == 0) {
        int tot = 0;
#pragma unroll
        for (int k = 0; k < 8; k++) tot += ws[k];
        g_bsum[boff + blk] = tot;
    }
}

__global__ __launch_bounds__(1024) void k_scanB(int n, int boff, int sidx,
                                                float* __restrict__ numOut) {
    __shared__ int sh[1024];
    int t = threadIdx.x;
    int carry = 0;
    for (int base = 0; base < n; base += 1024) {
        int v = (base + t < n) ? g_bsum[boff + base + t] : 0;
        sh[t] = v;
        __syncthreads();
        for (int off = 1; off < 1024; off <<= 1) {
            int a = (t >= off) ? sh[t - off] : 0;
            __syncthreads();
            sh[t] += a;
            __syncthreads();
        }
        if (base + t < n) g_bsum[boff + base + t] = sh[t] - v + carry;
        int ctot = sh[1023];
        __syncthreads();
        carry += ctot;
    }
    if (t == 0) {
        g_num[sidx] = carry;
        *numOut = (float)carry;
    }
}

__global__ __launch_bounds__(256) void k_scanC(int woff, int boff) {
    int t = threadIdx.x, blk = blockIdx.x;
    int lane = t & 31, warp = t >> 5;
    const uint4* bm = (const uint4*)(g_bitmap + woff);
    uint4 w = bm[blk * 256 + t];
    int p0 = __popc(w.x), p1 = __popc(w.y), p2 = __popc(w.z), p3 = __popc(w.w);
    int ts = p0 + p1 + p2 + p3;
    int incl = ts;
    for (int o = 1; o < 32; o <<= 1) {
        int v = __shfl_up_sync(0xffffffffu, incl, o);
        if (lane >= o) incl += v;
    }
    __shared__ int ws[8], wb[8];
    if (lane == 31) ws[warp] = incl;
    __syncthreads();
    if (t == 0) {
        int acc = 0;
#pragma unroll
        for (int k = 0; k < 8; k++) {
            wb[k] = acc;
            acc += ws[k];
        }
    }
    __syncthreads();
    int ex = g_bsum[boff + blk] + wb[warp] + (incl - ts);
    uint4 o4;
    o4.x = ex;
    o4.y = ex + p0;
    o4.z = ex + p0 + p1;
    o4.w = ex + p0 + p1 + p2;
    ((uint4*)(g_wpre + woff))[blk * 256 + t] = o4;
}

__global__ __launch_bounds__(256) void k_inv(float* __restrict__ out) {
    int idx = blockIdx.x * blockDim.x + threadIdx.x;
    if (idx >= 3 * NPTS) return;
    int s = idx / NPTS;
    int i = idx - s * NPTS;
    int key = g_keys[idx];
    int woff = (s == 0) ? WOFF0 : ((s == 1) ? WOFF1 : WOFF2);
    int w = woff + (key >> 5);
    int rank = (int)g_wpre[w] + __popc(g_bitmap[w] & ((1u << (key & 31)) - 1u));
    out[(long long)s * OUTSTRIDE + 8000000 + i] = (float)rank;
}

template <int S>
__global__ __launch_bounds__(256) void k_scatter(float* __restrict__ out) {
    constexpr int D0 = (S == 0) ? 240 : (S == 1) ? 120 : 480;
    constexpr int D1 = (S == 0) ? 180 : (S == 1) ? 90 : 360;
    constexpr int D2 = (S == 0) ? 16 : (S == 1) ? 8 : 32;
    constexpr int WOFF = (S == 0) ? WOFF0 : (S == 1) ? WOFF1 : WOFF2;
    constexpr int NW = (S == 0) ? W0 : (S == 1) ? W1 : W2;
    int w = blockIdx.x * blockDim.x + threadIdx.x;
    if (w >= NW) return;
    unsigned word = g_bitmap[WOFF + w];
    if (!word) return;
    int rank = (int)g_wpre[WOFF + w];
    float* cb = out + (long long)S * OUTSTRIDE + 10000000;
    int keyBase = w << 5;
    while (word) {
        int bit = __ffs(word) - 1;
        word &= word - 1;
        int key = keyBase + bit;
        int z = key % D2;
        int t1 = key / D2;
        int y = t1 % D1;
        int t2 = t1 / D1;
        int x = t2 % D0;
        int b = t2 / D0;
        float* row = cb + 4ll * rank;
        row[0] = (float)b;
        row[1] = (float)z;
        row[2] = (float)y;
        row[3] = (float)x;
        rank++;
    }
}

__global__ __launch_bounds__(256) void k_ztail(float* __restrict__ out, int sidx) {
    int idx = blockIdx.x * blockDim.x + threadIdx.x;
    if (idx >= 8000000) return;
    int lim = 4 * g_num[sidx];
    if (idx >= lim) out[(long long)sidx * OUTSTRIDE + 10000000 + idx] = 0.0f;
}

extern "C" void kernel_launch(void* const* d_in, const int* in_sizes, int n_in,
                              void* d_out, int out_size) {
    const float4* pts = (const float4*)d_in[0];
    const int* batch = (const int*)d_in[1];
    for (int i = 0; i < n_in; i++) {
        if (in_sizes[i] == 8000000) pts = (const float4*)d_in[i];
        else if (in_sizes[i] == 2000000) batch = (const int*)d_in[i];
    }
    float* out = (float*)d_out;

    k_clear<<<(TOTW / 4 + 255) / 256, 256>>>();
    k_points<<<(NPTS + 255) / 256, 256>>>(pts, batch, out);

    k_scanA<<<B0, 256>>>(WOFF0, BOFF0);
    k_scanA<<<B1, 256>>>(WOFF1, BOFF1);
    k_scanA<<<B2, 256>>>(WOFF2, BOFF2);

    k_scanB<<<1, 1024>>>(B0, BOFF0, 0, out + 0 * OUTSTRIDE + 18000000ll);
    k_scanB<<<1, 1024>>>(B1, BOFF1, 1, out + 1 * OUTSTRIDE + 18000000ll);
    k_scanB<<<1, 1024>>>(B2, BOFF2, 2, out + 2 * OUTSTRIDE + 18000000ll);

    k_scanC<<<B0, 256>>>(WOFF0, BOFF0);
    k_scanC<<<B1, 256>>>(WOFF1, BOFF1);
    k_scanC<<<B2, 256>>>(WOFF2, BOFF2);

    k_inv<<<(3 * NPTS + 255) / 256, 256>>>(out);

    k_scatter<0><<<(W0 + 255) / 256, 256>>>(out);
    k_scatter<1><<<(W1 + 255) / 256, 256>>>(out);
    k_scatter<2><<<(W2 + 255) / 256, 256>>>(out);

    k_ztail<<<(8000000 + 255) / 256, 256>>>(out, 0);
    k_ztail<<<(8000000 + 255) / 256, 256>>>(out, 1);
    k_ztail<<<(8000000 + 255) / 256, 256>>>(out, 2);
}

// round 14
// speedup vs baseline: 1.0383x; 1.0383x over previous
#include <cuda_runtime.h>

// ---------------------------------------------------------------------------
// voxelization: 3 scales (2, 4, 1), spatial_shape (480, 360, 32), batch 8
// Output is ONE float32 buffer; per scale s (stride 18,000,001 f32):
//   [0, 8M)  bxyz (N x 4) | [8M, 10M) inv (N) | [10M, 18M) coors | [18M] num
// OUTSTRIDE is odd -> only 32-bit stores into out.
// FP model (verified EXACT in round 13, rel_err = 0.0):
//   r2  = fl(fl(x*x) + fl(y*y)); rho = IEEE sqrt
//   phi = strict no-FMA Sun/fdlibm atan2f (glibc flt-32)
//   bin = floor(((clip(v)-lo) * fl(1/crop)) * cells)
// 6 launches: init, points, scanA, scanB, scanC, inv+scatter.
// ---------------------------------------------------------------------------

#define NPTS 2000000
#define OUTSTRIDE 18000001ll

#define W0 173056
#define W1 22528
#define W2 1382400
#define WOFF0 0
#define WOFF1 173056
#define WOFF2 195584
#define TOTW 1577984
#define NBLK 1541          // total 1024-word blocks (169 + 22 + 1350)
#define SEG1 169
#define SEG2 191

// inv+scatter fused kernel block ranges
#define NB_INV 23438       // ceil(6M / 256)
#define NB_S0 676          // W0/256
#define NB_S1 88           // W1/256
#define NB_S2 5400         // W2/256

static __device__ unsigned g_bitmap[TOTW];
static __device__ unsigned g_wpre[TOTW];
static __device__ int g_keys[3 * NPTS];
static __device__ int g_bsum[NBLK];
static __device__ int g_num[3];

// ---------------------------------------------------------------------------
// Bit-exact glibc flt-32 (Sun fdlibm) atanf/atan2f, strict FP (no contraction)
// ---------------------------------------------------------------------------
__device__ __forceinline__ float fdl_atanf(float xin) {
    unsigned hx = __float_as_uint(xin);
    unsigned ix = hx & 0x7fffffffu;
    float x = xin;
    int id;
    if (ix >= 0x4c800000u) {
        if (ix > 0x7f800000u) return __fadd_rn(xin, xin);
        float r = __fadd_rn(__uint_as_float(0x3fc90fdau), __uint_as_float(0x33a22168u));
        return (hx >> 31) ? -r : r;
    }
    if (ix < 0x3ee00000u) {
        if (ix < 0x39800000u) return xin;
        id = -1;
    } else {
        x = fabsf(x);
        if (ix < 0x3f980000u) {
            if (ix < 0x3f300000u) {
                id = 0;
                x = __fdiv_rn(__fsub_rn(__fmul_rn(2.0f, x), 1.0f), __fadd_rn(2.0f, x));
            } else {
                id = 1;
                x = __fdiv_rn(__fsub_rn(x, 1.0f), __fadd_rn(x, 1.0f));
            }
        } else {
            if (ix < 0x401c0000u) {
                id = 2;
                x = __fdiv_rn(__fsub_rn(x, 1.5f), __fadd_rn(1.0f, __fmul_rn(1.5f, x)));
            } else {
                id = 3;
                x = __fdiv_rn(-1.0f, x);
            }
        }
    }
    float z = __fmul_rn(x, x);
    float w = __fmul_rn(z, z);
    const float a0 = (float)3.33333333333329318027e-01;
    const float a1 = (float)-1.99999999998764832476e-01;
    const float a2 = (float)1.42857142725034663711e-01;
    const float a3 = (float)-1.11111104054623557880e-01;
    const float a4 = (float)9.09088713343650656196e-02;
    const float a5 = (float)-7.69187620504482999495e-02;
    const float a6 = (float)6.66107313738753120669e-02;
    const float a7 = (float)-5.83357013379057348645e-02;
    const float a8 = (float)4.97687799461593236017e-02;
    const float a9 = (float)-3.65315727442169155270e-02;
    const float a10 = (float)1.62858201153657823623e-02;
    float s1 = __fmul_rn(w, a10);
    s1 = __fadd_rn(a8, s1);
    s1 = __fmul_rn(w, s1);
    s1 = __fadd_rn(a6, s1);
    s1 = __fmul_rn(w, s1);
    s1 = __fadd_rn(a4, s1);
    s1 = __fmul_rn(w, s1);
    s1 = __fadd_rn(a2, s1);
    s1 = __fmul_rn(w, s1);
    s1 = __fadd_rn(a0, s1);
    s1 = __fmul_rn(z, s1);
    float s2 = __fmul_rn(w, a9);
    s2 = __fadd_rn(a7, s2);
    s2 = __fmul_rn(w, s2);
    s2 = __fadd_rn(a5, s2);
    s2 = __fmul_rn(w, s2);
    s2 = __fadd_rn(a3, s2);
    s2 = __fmul_rn(w, s2);
    s2 = __fadd_rn(a1, s2);
    s2 = __fmul_rn(w, s2);
    float s = __fadd_rn(s1, s2);
    if (id < 0) return __fsub_rn(x, __fmul_rn(x, s));
    float hi = __uint_as_float(id == 0 ? 0x3eed6338u : id == 1 ? 0x3f490fdau
                               : id == 2 ? 0x3f7b985eu : 0x3fc90fdau);
    float lo = __uint_as_float(id == 0 ? 0x31ac3769u : id == 1 ? 0x33222168u
                               : id == 2 ? 0x33140fb4u : 0x33a22168u);
    float t1 = __fsub_rn(__fmul_rn(x, s), lo);
    float zr = __fsub_rn(hi, __fsub_rn(t1, x));
    return (hx >> 31) ? -zr : zr;
}

__device__ __forceinline__ float fdl_atan2f(float y, float x) {
    unsigned hx = __float_as_uint(x), ix = hx & 0x7fffffffu;
    unsigned hy = __float_as_uint(y), iy = hy & 0x7fffffffu;
    const float pi = __uint_as_float(0x40490fdbu);
    const float pi_lo = __uint_as_float(0xb3bbbd2eu);
    const float pi_o_2 = __uint_as_float(0x3fc90fdbu);
    if (ix > 0x7f800000u || iy > 0x7f800000u) return __fadd_rn(x, y);
    if (hx == 0x3f800000u) return fdl_atanf(y);
    unsigned m = ((hy >> 31) & 1u) | ((hx >> 30) & 2u);
    if (iy == 0u) {
        switch (m) { case 0: case 1: return y; case 2: return pi; default: return -pi; }
    }
    if (ix == 0u) return (hy >> 31) ? -pi_o_2 : pi_o_2;
    if (ix == 0x7f800000u) {
        if (iy == 0x7f800000u) {
            float q = __fmul_rn(pi_o_2, 0.5f);
            switch (m) { case 0: return q; case 1: return -q;
                         case 2: return __fmul_rn(3.0f, q); default: return -__fmul_rn(3.0f, q); }
        } else {
            switch (m) { case 0: return 0.0f; case 1: return -0.0f;
                         case 2: return pi; default: return -pi; }
        }
    }
    if (iy == 0x7f800000u) return (hy >> 31) ? -pi_o_2 : pi_o_2;
    int k = ((int)iy - (int)ix) >> 23;
    float z;
    if (k > 26) {
        z = __fadd_rn(pi_o_2, __fmul_rn(0.5f, pi_lo));
        m &= 1u;
    } else if ((hx >> 31) && k < -26) {
        z = 0.0f;
    } else {
        z = fdl_atanf(fabsf(__fdiv_rn(y, x)));
    }
    switch (m) {
        case 0: return z;
        case 1: return -z;
        case 2: return __fsub_rn(pi, __fsub_rn(z, pi_lo));
        default: return __fsub_rn(__fsub_rn(z, pi_lo), pi);
    }
}

__device__ __forceinline__ int gidx_r(float v, float lo, float hi,
                                      float invcrop, float cells) {
    float c = fminf(fmaxf(v, lo), hi);
    float t = __fsub_rn(c, lo);
    float u = __fmul_rn(t, invcrop);
    float g = __fmul_rn(u, cells);
    return (int)floorf(g);
}

// init: zero bitmap (uint4) + zero all 3 coors regions (scalar, misaligned base)
#define INIT_BM (TOTW / 4)              // 394496 uint4 slots
#define INIT_TOT (INIT_BM + 24000000)   // + 3 x 8M coors floats
__global__ __launch_bounds__(256) void k_init(float* __restrict__ out) {
    int i = blockIdx.x * blockDim.x + threadIdx.x;
    if (i < INIT_BM) {
        ((uint4*)g_bitmap)[i] = make_uint4(0, 0, 0, 0);
    } else {
        int j = i - INIT_BM;
        if (j < 24000000) {
            int s = j >> 23;            // j / 8388608 -- NOT 8M decimal; fix below
            // careful: use exact division by 8,000,000
            s = j / 8000000;
            int k = j - s * 8000000;
            out[(long long)s * OUTSTRIDE + 10000000 + k] = 0.0f;
        }
    }
}

__global__ __launch_bounds__(256) void k_points(const float4* __restrict__ pts,
                                                const int* __restrict__ batch,
                                                float* __restrict__ out) {
    int i = blockIdx.x * blockDim.x + threadIdx.x;
    if (i >= NPTS) return;
    float4 p = pts[i];
    int b = batch[i];
    float r2 = __fadd_rn(__fmul_rn(p.x, p.x), __fmul_rn(p.y, p.y));
    float rho = __fsqrt_rn(r2);
    float phi = fdl_atan2f(p.y, p.x);
    const float PI = 3.14159265358979323846f;
    const float TWO_PI = __fadd_rn(PI, PI);
    const int D0[3] = {240, 120, 480};
    const int D1[3] = {180, 90, 360};
    const int D2[3] = {16, 8, 32};
    const float CX[3] = {239.f, 119.f, 479.f};
    const float CY[3] = {179.f, 89.f, 359.f};
    const float CZ[3] = {15.f, 7.f, 31.f};
    const int WF[3] = {WOFF0, WOFF1, WOFF2};
    const float INV_X = __fdiv_rn(1.0f, 50.0f);
    const float INV_Y = __fdiv_rn(1.0f, TWO_PI);
    const float INV_Z = __fdiv_rn(1.0f, 6.0f);
    float bf = (float)b;
#pragma unroll
    for (int s = 0; s < 3; s++) {
        int gx = gidx_r(rho, 0.f, 50.f, INV_X, CX[s]);
        int gy = gidx_r(phi, -PI, PI, INV_Y, CY[s]);
        int gz = gidx_r(p.z, -4.f, 2.f, INV_Z, CZ[s]);
        int key = ((b * D0[s] + gx) * D1[s] + gy) * D2[s] + gz;
        g_keys[s * NPTS + i] = key;
        atomicOr(&g_bitmap[WF[s] + (key >> 5)], 1u << (key & 31));
        float* row = out + (long long)s * OUTSTRIDE + 4ll * i;
        row[0] = bf;
        row[1] = (float)gx;
        row[2] = (float)gy;
        row[3] = (float)gz;
    }
}

// scanA: one block per 1024 bitmap words (segments are block-aligned)
__global__ __launch_bounds__(256) void k_scanA() {
    int t = threadIdx.x, blk = blockIdx.x;
    uint4 w = ((const uint4*)g_bitmap)[blk * 256 + t];
    int s = __popc(w.x) + __popc(w.y) + __popc(w.z) + __popc(w.w);
    for (int o = 16; o; o >>= 1) s += __shfl_down_sync(0xffffffffu, s, o);
    __shared__ int ws[8];
    if ((t & 31) == 0) ws[t >> 5] = s;
    __syncthreads();
    if (t == 0) {
        int tot = 0;
#pragma unroll
        for (int k = 0; k < 8; k++) tot += ws[k];
        g_bsum[blk] = tot;
    }
}

// scanB: 3 blocks, block s scans its g_bsum segment exclusively, writes num
__global__ __launch_bounds__(1024) void k_scanB(float* __restrict__ out) {
    int s = blockIdx.x;
    int start = (s == 0) ? 0 : (s == 1) ? SEG1 : SEG2;
    int n = (s == 0) ? SEG1 : (s == 1) ? (SEG2 - SEG1) : (NBLK - SEG2);
    __shared__ int sh[1024];
    int t = threadIdx.x;
    int carry = 0;
    for (int base = 0; base < n; base += 1024) {
        int v = (base + t < n) ? g_bsum[start + base + t] : 0;
        sh[t] = v;
        __syncthreads();
        for (int off = 1; off < 1024; off <<= 1) {
            int a = (t >= off) ? sh[t - off] : 0;
            __syncthreads();
            sh[t] += a;
            __syncthreads();
        }
        if (base + t < n) g_bsum[start + base + t] = sh[t] - v + carry;
        int ctot = sh[1023];
        __syncthreads();
        carry += ctot;
    }
    if (t == 0) {
        g_num[s] = carry;
        out[(long long)s * OUTSTRIDE + 18000000] = (float)carry;
    }
}

// scanC: per-word exclusive popcount prefix using scanned block offsets
__global__ __launch_bounds__(256) void k_scanC() {
    int t = threadIdx.x, blk = blockIdx.x;
    int lane = t & 31, warp = t >> 5;
    uint4 w = ((const uint4*)g_bitmap)[blk * 256 + t];
    int p0 = __popc(w.x), p1 = __popc(w.y), p2 = __popc(w.z), p3 = __popc(w.w);
    int ts = p0 + p1 + p2 + p3;
    int incl = ts;
    for (int o = 1; o < 32; o <<= 1) {
        int v = __shfl_up_sync(0xffffffffu, incl, o);
        if (lane >= o) incl += v;
    }
    __shared__ int ws[8], wb[8];
    if (lane == 31) ws[warp] = incl;
    __syncthreads();
    if (t == 0) {
        int acc = 0;
#pragma unroll
        for (int k = 0; k < 8; k++) {
            wb[k] = acc;
            acc += ws[k];
        }
    }
    __syncthreads();
    int ex = g_bsum[blk] + wb[warp] + (incl - ts);
    uint4 o4;
    o4.x = ex;
    o4.y = ex + p0;
    o4.z = ex + p0 + p1;
    o4.w = ex + p0 + p1 + p2;
    ((uint4*)g_wpre)[blk * 256 + t] = o4;
}

template <int S>
__device__ __forceinline__ void scatter_words(int w, float* __restrict__ out) {
    constexpr int D0 = (S == 0) ? 240 : (S == 1) ? 120 : 480;
    constexpr int D1 = (S == 0) ? 180 : (S == 1) ? 90 : 360;
    constexpr int D2 = (S == 0) ? 16 : (S == 1) ? 8 : 32;
    constexpr int WOFF = (S == 0) ? WOFF0 : (S == 1) ? WOFF1 : WOFF2;
    unsigned word = g_bitmap[WOFF + w];
    if (!word) return;
    int rank = (int)g_wpre[WOFF + w];
    float* cb = out + (long long)S * OUTSTRIDE + 10000000;
    int keyBase = w << 5;
    while (word) {
        int bit = __ffs(word) - 1;
        word &= word - 1;
        int key = keyBase + bit;
        int z = key % D2;
        int t1 = key / D2;
        int y = t1 % D1;
        int t2 = t1 / D1;
        int x = t2 % D0;
        int b = t2 / D0;
        float* row = cb + 4ll * rank;
        row[0] = (float)b;
        row[1] = (float)z;
        row[2] = (float)y;
        row[3] = (float)x;
        rank++;
    }
}

// fused inv + scatter: blocks [0, NB_INV) do inv, rest do per-scale scatter
__global__ __launch_bounds__(256) void k_invscat(float* __restrict__ out) {
    int blk = blockIdx.x, t = threadIdx.x;
    if (blk < NB_INV) {
        int idx = blk * 256 + t;
        if (idx >= 3 * NPTS) return;
        int s = idx / NPTS;
        int i = idx - s * NPTS;
        int key = g_keys[idx];
        int woff = (s == 0) ? WOFF0 : ((s == 1) ? WOFF1 : WOFF2);
        int w = woff + (key >> 5);
        int rank = (int)g_wpre[w] + __popc(g_bitmap[w] & ((1u << (key & 31)) - 1u));
        out[(long long)s * OUTSTRIDE + 8000000 + i] = (float)rank;
    } else {
        int sb = blk - NB_INV;
        if (sb < NB_S0) {
            scatter_words<0>(sb * 256 + t, out);
        } else if (sb < NB_S0 + NB_S1) {
            scatter_words<1>((sb - NB_S0) * 256 + t, out);
        } else {
            scatter_words<2>((sb - NB_S0 - NB_S1) * 256 + t, out);
        }
    }
}

extern "C" void kernel_launch(void* const* d_in, const int* in_sizes, int n_in,
                              void* d_out, int out_size) {
    const float4* pts = (const float4*)d_in[0];
    const int* batch = (const int*)d_in[1];
    for (int i = 0; i < n_in; i++) {
        if (in_sizes[i] == 8000000) pts = (const float4*)d_in[i];
        else if (in_sizes[i] == 2000000) batch = (const int*)d_in[i];
    }
    float* out = (float*)d_out;

    k_init<<<(INIT_TOT + 255) / 256, 256>>>(out);
    k_points<<<(NPTS + 255) / 256, 256>>>(pts, batch, out);
    k_scanA<<<NBLK, 256>>>();
    k_scanB<<<3, 1024>>>(out);
    k_scanC<<<NBLK, 256>>>();
    k_invscat<<<NB_INV + NB_S0 + NB_S1 + NB_S2, 256>>>(out);
}

// round 15
// speedup vs baseline: 1.1917x; 1.1477x over previous
#include <cuda_runtime.h>

// ---------------------------------------------------------------------------
// voxelization: 3 scales (2, 4, 1), spatial_shape (480, 360, 32), batch 8
// Output is ONE float32 buffer; per scale s (stride 18,000,001 f32):
//   [0, 8M)  bxyz (N x 4) | [8M, 10M) inv (N) | [10M, 18M) coors | [18M] num
// OUTSTRIDE is odd -> only 32-bit stores into out.
// FP model (verified EXACT, rel_err = 0.0):
//   r2  = fl(fl(x*x) + fl(y*y)); rho = IEEE sqrt
//   phi = strict no-FMA Sun/fdlibm atan2f (glibc flt-32)
//   bin = floor(((clip(v)-lo) * fl(1/crop)) * cells)
// 6 launches: init(bitmap), points(smem-transposed stores), scanA, scanB,
//             scanC, inv+scatter+ztail.
// ---------------------------------------------------------------------------

#define NPTS 2000000
#define OUTSTRIDE 18000001ll

#define W0 173056
#define W1 22528
#define W2 1382400
#define WOFF0 0
#define WOFF1 173056
#define WOFF2 195584
#define TOTW 1577984
#define NBLK 1541          // 1024-word bitmap blocks (169 + 22 + 1350)
#define SEG1 169
#define SEG2 191

// invscat block ranges
#define NB_INV 23438       // ceil(6M / 256)   inv
#define NB_S0 676          // W0/256           scatter scale idx 0
#define NB_S1 88           // W1/256           scatter scale idx 1
#define NB_S2 5400         // W2/256           scatter scale idx 2
#define NB_Z 31250         // 8M/256           ztail per scale

static __device__ unsigned g_bitmap[TOTW];
static __device__ unsigned g_wpre[TOTW];
static __device__ int g_keys[3 * NPTS];
static __device__ int g_bsum[NBLK];
static __device__ int g_num[3];

// ---------------------------------------------------------------------------
// Bit-exact glibc flt-32 (Sun fdlibm) atanf/atan2f, strict FP (no contraction)
// ---------------------------------------------------------------------------
__device__ __forceinline__ float fdl_atanf(float xin) {
    unsigned hx = __float_as_uint(xin);
    unsigned ix = hx & 0x7fffffffu;
    float x = xin;
    int id;
    if (ix >= 0x4c800000u) {
        if (ix > 0x7f800000u) return __fadd_rn(xin, xin);
        float r = __fadd_rn(__uint_as_float(0x3fc90fdau), __uint_as_float(0x33a22168u));
        return (hx >> 31) ? -r : r;
    }
    if (ix < 0x3ee00000u) {
        if (ix < 0x39800000u) return xin;
        id = -1;
    } else {
        x = fabsf(x);
        if (ix < 0x3f980000u) {
            if (ix < 0x3f300000u) {
                id = 0;
                x = __fdiv_rn(__fsub_rn(__fmul_rn(2.0f, x), 1.0f), __fadd_rn(2.0f, x));
            } else {
                id = 1;
                x = __fdiv_rn(__fsub_rn(x, 1.0f), __fadd_rn(x, 1.0f));
            }
        } else {
            if (ix < 0x401c0000u) {
                id = 2;
                x = __fdiv_rn(__fsub_rn(x, 1.5f), __fadd_rn(1.0f, __fmul_rn(1.5f, x)));
            } else {
                id = 3;
                x = __fdiv_rn(-1.0f, x);
            }
        }
    }
    float z = __fmul_rn(x, x);
    float w = __fmul_rn(z, z);
    const float a0 = (float)3.33333333333329318027e-01;
    const float a1 = (float)-1.99999999998764832476e-01;
    const float a2 = (float)1.42857142725034663711e-01;
    const float a3 = (float)-1.11111104054623557880e-01;
    const float a4 = (float)9.09088713343650656196e-02;
    const float a5 = (float)-7.69187620504482999495e-02;
    const float a6 = (float)6.66107313738753120669e-02;
    const float a7 = (float)-5.83357013379057348645e-02;
    const float a8 = (float)4.97687799461593236017e-02;
    const float a9 = (float)-3.65315727442169155270e-02;
    const float a10 = (float)1.62858201153657823623e-02;
    float s1 = __fmul_rn(w, a10);
    s1 = __fadd_rn(a8, s1);
    s1 = __fmul_rn(w, s1);
    s1 = __fadd_rn(a6, s1);
    s1 = __fmul_rn(w, s1);
    s1 = __fadd_rn(a4, s1);
    s1 = __fmul_rn(w, s1);
    s1 = __fadd_rn(a2, s1);
    s1 = __fmul_rn(w, s1);
    s1 = __fadd_rn(a0, s1);
    s1 = __fmul_rn(z, s1);
    float s2 = __fmul_rn(w, a9);
    s2 = __fadd_rn(a7, s2);
    s2 = __fmul_rn(w, s2);
    s2 = __fadd_rn(a5, s2);
    s2 = __fmul_rn(w, s2);
    s2 = __fadd_rn(a3, s2);
    s2 = __fmul_rn(w, s2);
    s2 = __fadd_rn(a1, s2);
    s2 = __fmul_rn(w, s2);
    float s = __fadd_rn(s1, s2);
    if (id < 0) return __fsub_rn(x, __fmul_rn(x, s));
    float hi = __uint_as_float(id == 0 ? 0x3eed6338u : id == 1 ? 0x3f490fdau
                               : id == 2 ? 0x3f7b985eu : 0x3fc90fdau);
    float lo = __uint_as_float(id == 0 ? 0x31ac3769u : id == 1 ? 0x33222168u
                               : id == 2 ? 0x33140fb4u : 0x33a22168u);
    float t1 = __fsub_rn(__fmul_rn(x, s), lo);
    float zr = __fsub_rn(hi, __fsub_rn(t1, x));
    return (hx >> 31) ? -zr : zr;
}

__device__ __forceinline__ float fdl_atan2f(float y, float x) {
    unsigned hx = __float_as_uint(x), ix = hx & 0x7fffffffu;
    unsigned hy = __float_as_uint(y), iy = hy & 0x7fffffffu;
    const float pi = __uint_as_float(0x40490fdbu);
    const float pi_lo = __uint_as_float(0xb3bbbd2eu);
    const float pi_o_2 = __uint_as_float(0x3fc90fdbu);
    if (ix > 0x7f800000u || iy > 0x7f800000u) return __fadd_rn(x, y);
    if (hx == 0x3f800000u) return fdl_atanf(y);
    unsigned m = ((hy >> 31) & 1u) | ((hx >> 30) & 2u);
    if (iy == 0u) {
        switch (m) { case 0: case 1: return y; case 2: return pi; default: return -pi; }
    }
    if (ix == 0u) return (hy >> 31) ? -pi_o_2 : pi_o_2;
    if (ix == 0x7f800000u) {
        if (iy == 0x7f800000u) {
            float q = __fmul_rn(pi_o_2, 0.5f);
            switch (m) { case 0: return q; case 1: return -q;
                         case 2: return __fmul_rn(3.0f, q); default: return -__fmul_rn(3.0f, q); }
        } else {
            switch (m) { case 0: return 0.0f; case 1: return -0.0f;
                         case 2: return pi; default: return -pi; }
        }
    }
    if (iy == 0x7f800000u) return (hy >> 31) ? -pi_o_2 : pi_o_2;
    int k = ((int)iy - (int)ix) >> 23;
    float z;
    if (k > 26) {
        z = __fadd_rn(pi_o_2, __fmul_rn(0.5f, pi_lo));
        m &= 1u;
    } else if ((hx >> 31) && k < -26) {
        z = 0.0f;
    } else {
        z = fdl_atanf(fabsf(__fdiv_rn(y, x)));
    }
    switch (m) {
        case 0: return z;
        case 1: return -z;
        case 2: return __fsub_rn(pi, __fsub_rn(z, pi_lo));
        default: return __fsub_rn(__fsub_rn(z, pi_lo), pi);
    }
}

__device__ __forceinline__ int gidx_r(float v, float lo, float hi,
                                      float invcrop, float cells) {
    float c = fminf(fmaxf(v, lo), hi);
    float t = __fsub_rn(c, lo);
    float u = __fmul_rn(t, invcrop);
    float g = __fmul_rn(u, cells);
    return (int)floorf(g);
}

// init: zero bitmap only (coors tail now zeroed in invscat)
__global__ __launch_bounds__(256) void k_init() {
    int i = blockIdx.x * blockDim.x + threadIdx.x;
    if (i < TOTW / 4) ((uint4*)g_bitmap)[i] = make_uint4(0, 0, 0, 0);
}

// points: compute bins, stage rows in smem, write coalesced full-sector runs
__global__ __launch_bounds__(256) void k_points(const float4* __restrict__ pts,
                                                const int* __restrict__ batch,
                                                float* __restrict__ out) {
    __shared__ float sbuf[3][1024];
    int blk = blockIdx.x, t = threadIdx.x;
    int i = blk * 256 + t;
    if (i < NPTS) {
        float4 p = pts[i];
        int b = batch[i];
        float r2 = __fadd_rn(__fmul_rn(p.x, p.x), __fmul_rn(p.y, p.y));
        float rho = __fsqrt_rn(r2);
        float phi = fdl_atan2f(p.y, p.x);
        const float PI = 3.14159265358979323846f;
        const float TWO_PI = __fadd_rn(PI, PI);
        const int D0[3] = {240, 120, 480};
        const int D1[3] = {180, 90, 360};
        const int D2[3] = {16, 8, 32};
        const float CX[3] = {239.f, 119.f, 479.f};
        const float CY[3] = {179.f, 89.f, 359.f};
        const float CZ[3] = {15.f, 7.f, 31.f};
        const int WF[3] = {WOFF0, WOFF1, WOFF2};
        const float INV_X = __fdiv_rn(1.0f, 50.0f);
        const float INV_Y = __fdiv_rn(1.0f, TWO_PI);
        const float INV_Z = __fdiv_rn(1.0f, 6.0f);
        float bf = (float)b;
#pragma unroll
        for (int s = 0; s < 3; s++) {
            int gx = gidx_r(rho, 0.f, 50.f, INV_X, CX[s]);
            int gy = gidx_r(phi, -PI, PI, INV_Y, CY[s]);
            int gz = gidx_r(p.z, -4.f, 2.f, INV_Z, CZ[s]);
            int key = ((b * D0[s] + gx) * D1[s] + gy) * D2[s] + gz;
            g_keys[s * NPTS + i] = key;
            atomicOr(&g_bitmap[WF[s] + (key >> 5)], 1u << (key & 31));
            sbuf[s][t * 4 + 0] = bf;
            sbuf[s][t * 4 + 1] = (float)gx;
            sbuf[s][t * 4 + 2] = (float)gy;
            sbuf[s][t * 4 + 3] = (float)gz;
        }
    }
    __syncthreads();
    // coalesced write-out: 4 consecutive-address passes per scale
    long long ebase = (long long)blk * 1024;
#pragma unroll
    for (int s = 0; s < 3; s++) {
        float* base = out + (long long)s * OUTSTRIDE + ebase;
#pragma unroll
        for (int p = 0; p < 4; p++) {
            int el = p * 256 + t;
            if (ebase + el < 4ll * NPTS) base[el] = sbuf[s][el];
        }
    }
}

// scanA: one block per 1024 bitmap words
__global__ __launch_bounds__(256) void k_scanA() {
    int t = threadIdx.x, blk = blockIdx.x;
    uint4 w = ((const uint4*)g_bitmap)[blk * 256 + t];
    int s = __popc(w.x) + __popc(w.y) + __popc(w.z) + __popc(w.w);
    for (int o = 16; o; o >>= 1) s += __shfl_down_sync(0xffffffffu, s, o);
    __shared__ int ws[8];
    if ((t & 31) == 0) ws[t >> 5] = s;
    __syncthreads();
    if (t == 0) {
        int tot = 0;
#pragma unroll
        for (int k = 0; k < 8; k++) tot += ws[k];
        g_bsum[blk] = tot;
    }
}

// scanB: 3 blocks, block s scans its g_bsum segment exclusively, writes num
__global__ __launch_bounds__(1024) void k_scanB(float* __restrict__ out) {
    int s = blockIdx.x;
    int start = (s == 0) ? 0 : (s == 1) ? SEG1 : SEG2;
    int n = (s == 0) ? SEG1 : (s == 1) ? (SEG2 - SEG1) : (NBLK - SEG2);
    __shared__ int sh[1024];
    int t = threadIdx.x;
    int carry = 0;
    for (int base = 0; base < n; base += 1024) {
        int v = (base + t < n) ? g_bsum[start + base + t] : 0;
        sh[t] = v;
        __syncthreads();
        for (int off = 1; off < 1024; off <<= 1) {
            int a = (t >= off) ? sh[t - off] : 0;
            __syncthreads();
            sh[t] += a;
            __syncthreads();
        }
        if (base + t < n) g_bsum[start + base + t] = sh[t] - v + carry;
        int ctot = sh[1023];
        __syncthreads();
        carry += ctot;
    }
    if (t == 0) {
        g_num[s] = carry;
        out[(long long)s * OUTSTRIDE + 18000000] = (float)carry;
    }
}

// scanC: per-word exclusive popcount prefix
__global__ __launch_bounds__(256) void k_scanC() {
    int t = threadIdx.x, blk = blockIdx.x;
    int lane = t & 31, warp = t >> 5;
    uint4 w = ((const uint4*)g_bitmap)[blk * 256 + t];
    int p0 = __popc(w.x), p1 = __popc(w.y), p2 = __popc(w.z), p3 = __popc(w.w);
    int ts = p0 + p1 + p2 + p3;
    int incl = ts;
    for (int o = 1; o < 32; o <<= 1) {
        int v = __shfl_up_sync(0xffffffffu, incl, o);
        if (lane >= o) incl += v;
    }
    __shared__ int ws[8], wb[8];
    if (lane == 31) ws[warp] = incl;
    __syncthreads();
    if (t == 0) {
        int acc = 0;
#pragma unroll
        for (int k = 0; k < 8; k++) {
            wb[k] = acc;
            acc += ws[k];
        }
    }
    __syncthreads();
    int ex = g_bsum[blk] + wb[warp] + (incl - ts);
    uint4 o4;
    o4.x = ex;
    o4.y = ex + p0;
    o4.z = ex + p0 + p1;
    o4.w = ex + p0 + p1 + p2;
    ((uint4*)g_wpre)[blk * 256 + t] = o4;
}

template <int S>
__device__ __forceinline__ void scatter_words(int w, float* __restrict__ out) {
    constexpr int D0 = (S == 0) ? 240 : (S == 1) ? 120 : 480;
    constexpr int D1 = (S == 0) ? 180 : (S == 1) ? 90 : 360;
    constexpr int D2 = (S == 0) ? 16 : (S == 1) ? 8 : 32;
    constexpr int WOFF = (S == 0) ? WOFF0 : (S == 1) ? WOFF1 : WOFF2;
    unsigned word = g_bitmap[WOFF + w];
    if (!word) return;
    int rank = (int)g_wpre[WOFF + w];
    float* cb = out + (long long)S * OUTSTRIDE + 10000000;
    int keyBase = w << 5;
    while (word) {
        int bit = __ffs(word) - 1;
        word &= word - 1;
        int key = keyBase + bit;
        int z = key % D2;
        int t1 = key / D2;
        int y = t1 % D1;
        int t2 = t1 / D1;
        int x = t2 % D0;
        int b = t2 / D0;
        float* row = cb + 4ll * rank;
        row[0] = (float)b;
        row[1] = (float)z;
        row[2] = (float)y;
        row[3] = (float)x;
        rank++;
    }
}

// fused inv + scatter + ztail
__global__ __launch_bounds__(256) void k_invscat(float* __restrict__ out) {
    int blk = blockIdx.x, t = threadIdx.x;
    if (blk < NB_INV) {
        int idx = blk * 256 + t;
        if (idx >= 3 * NPTS) return;
        int s = idx / NPTS;
        int i = idx - s * NPTS;
        int key = g_keys[idx];
        int woff = (s == 0) ? WOFF0 : ((s == 1) ? WOFF1 : WOFF2);
        int w = woff + (key >> 5);
        int rank = (int)g_wpre[w] + __popc(g_bitmap[w] & ((1u << (key & 31)) - 1u));
        out[(long long)s * OUTSTRIDE + 8000000 + i] = (float)rank;
        return;
    }
    int sb = blk - NB_INV;
    if (sb < NB_S0) { scatter_words<0>(sb * 256 + t, out); return; }
    sb -= NB_S0;
    if (sb < NB_S1) { scatter_words<1>(sb * 256 + t, out); return; }
    sb -= NB_S1;
    if (sb < NB_S2) { scatter_words<2>(sb * 256 + t, out); return; }
    sb -= NB_S2;
    // ztail: 3 x NB_Z blocks
    int s = sb / NB_Z;
    int zb = sb - s * NB_Z;
    int idx = zb * 256 + t;
    int lim = 4 * g_num[s];
    if (idx >= lim) out[(long long)s * OUTSTRIDE + 10000000 + idx] = 0.0f;
}

extern "C" void kernel_launch(void* const* d_in, const int* in_sizes, int n_in,
                              void* d_out, int out_size) {
    const float4* pts = (const float4*)d_in[0];
    const int* batch = (const int*)d_in[1];
    for (int i = 0; i < n_in; i++) {
        if (in_sizes[i] == 8000000) pts = (const float4*)d_in[i];
        else if (in_sizes[i] == 2000000) batch = (const int*)d_in[i];
    }
    float* out = (float*)d_out;

    k_init<<<NBLK, 256>>>();
    k_points<<<(NPTS + 255) / 256, 256>>>(pts, batch, out);
    k_scanA<<<NBLK, 256>>>();
    k_scanB<<<3, 1024>>>(out);
    k_scanC<<<NBLK, 256>>>();
    k_invscat<<<NB_INV + NB_S0 + NB_S1 + NB_S2 + 3 * NB_Z, 256>>>(out);
}

// round 16
// speedup vs baseline: 1.2589x; 1.0564x over previous
#include <cuda_runtime.h>

// ---------------------------------------------------------------------------
// voxelization: 3 scales (2, 4, 1), spatial_shape (480, 360, 32), batch 8
// Output is ONE float32 buffer; per scale s (stride 18,000,001 f32):
//   [0, 8M)  bxyz (N x 4) | [8M, 10M) inv (N) | [10M, 18M) coors | [18M] num
// OUTSTRIDE is odd -> only 32-bit stores into out.
// FP model (verified EXACT, rel_err = 0.0):
//   r2  = fl(fl(x*x) + fl(y*y)); rho = IEEE sqrt
//   phi = strict no-FMA Sun/fdlibm atan2f (glibc flt-32)
//   bin = floor(((clip(v)-lo) * fl(1/crop)) * cells)
// 4 launches: init, points, scan (decoupled lookback), inv+scatter+ztail.
// ---------------------------------------------------------------------------

#define NPTS 2000000
#define OUTSTRIDE 18000001ll

#define W0 173056
#define W1 22528
#define W2 1382400
#define WOFF0 0
#define WOFF1 173056
#define WOFF2 195584
#define TOTW 1577984
#define NBLK 1541          // 1024-word bitmap blocks (169 + 22 + 1350)
#define SEG1 169
#define SEG2 191

// invscat block ranges
#define NB_INV 5860        // 6M / 1024 els (4/thread)
#define NB_S0 676          // W0/256
#define NB_S1 88           // W1/256
#define NB_S2 5400         // W2/256
#define NB_Z 1954          // 8M / 4096 els (16/thread) per scale

static __device__ unsigned g_bitmap[TOTW];
static __device__ unsigned g_wpre[TOTW];
static __device__ int g_keys[3 * NPTS];
static __device__ unsigned long long g_desc[NBLK];
static __device__ int g_num[3];

// ---------------------------------------------------------------------------
// Bit-exact glibc flt-32 (Sun fdlibm) atanf/atan2f, strict FP (no contraction)
// ---------------------------------------------------------------------------
__device__ __forceinline__ float fdl_atanf(float xin) {
    unsigned hx = __float_as_uint(xin);
    unsigned ix = hx & 0x7fffffffu;
    float x = xin;
    int id;
    if (ix >= 0x4c800000u) {
        if (ix > 0x7f800000u) return __fadd_rn(xin, xin);
        float r = __fadd_rn(__uint_as_float(0x3fc90fdau), __uint_as_float(0x33a22168u));
        return (hx >> 31) ? -r : r;
    }
    if (ix < 0x3ee00000u) {
        if (ix < 0x39800000u) return xin;
        id = -1;
    } else {
        x = fabsf(x);
        if (ix < 0x3f980000u) {
            if (ix < 0x3f300000u) {
                id = 0;
                x = __fdiv_rn(__fsub_rn(__fmul_rn(2.0f, x), 1.0f), __fadd_rn(2.0f, x));
            } else {
                id = 1;
                x = __fdiv_rn(__fsub_rn(x, 1.0f), __fadd_rn(x, 1.0f));
            }
        } else {
            if (ix < 0x401c0000u) {
                id = 2;
                x = __fdiv_rn(__fsub_rn(x, 1.5f), __fadd_rn(1.0f, __fmul_rn(1.5f, x)));
            } else {
                id = 3;
                x = __fdiv_rn(-1.0f, x);
            }
        }
    }
    float z = __fmul_rn(x, x);
    float w = __fmul_rn(z, z);
    const float a0 = (float)3.33333333333329318027e-01;
    const float a1 = (float)-1.99999999998764832476e-01;
    const float a2 = (float)1.42857142725034663711e-01;
    const float a3 = (float)-1.11111104054623557880e-01;
    const float a4 = (float)9.09088713343650656196e-02;
    const float a5 = (float)-7.69187620504482999495e-02;
    const float a6 = (float)6.66107313738753120669e-02;
    const float a7 = (float)-5.83357013379057348645e-02;
    const float a8 = (float)4.97687799461593236017e-02;
    const float a9 = (float)-3.65315727442169155270e-02;
    const float a10 = (float)1.62858201153657823623e-02;
    float s1 = __fmul_rn(w, a10);
    s1 = __fadd_rn(a8, s1);
    s1 = __fmul_rn(w, s1);
    s1 = __fadd_rn(a6, s1);
    s1 = __fmul_rn(w, s1);
    s1 = __fadd_rn(a4, s1);
    s1 = __fmul_rn(w, s1);
    s1 = __fadd_rn(a2, s1);
    s1 = __fmul_rn(w, s1);
    s1 = __fadd_rn(a0, s1);
    s1 = __fmul_rn(z, s1);
    float s2 = __fmul_rn(w, a9);
    s2 = __fadd_rn(a7, s2);
    s2 = __fmul_rn(w, s2);
    s2 = __fadd_rn(a5, s2);
    s2 = __fmul_rn(w, s2);
    s2 = __fadd_rn(a3, s2);
    s2 = __fmul_rn(w, s2);
    s2 = __fadd_rn(a1, s2);
    s2 = __fmul_rn(w, s2);
    float s = __fadd_rn(s1, s2);
    if (id < 0) return __fsub_rn(x, __fmul_rn(x, s));
    float hi = __uint_as_float(id == 0 ? 0x3eed6338u : id == 1 ? 0x3f490fdau
                               : id == 2 ? 0x3f7b985eu : 0x3fc90fdau);
    float lo = __uint_as_float(id == 0 ? 0x31ac3769u : id == 1 ? 0x33222168u
                               : id == 2 ? 0x33140fb4u : 0x33a22168u);
    float t1 = __fsub_rn(__fmul_rn(x, s), lo);
    float zr = __fsub_rn(hi, __fsub_rn(t1, x));
    return (hx >> 31) ? -zr : zr;
}

__device__ __forceinline__ float fdl_atan2f(float y, float x) {
    unsigned hx = __float_as_uint(x), ix = hx & 0x7fffffffu;
    unsigned hy = __float_as_uint(y), iy = hy & 0x7fffffffu;
    const float pi = __uint_as_float(0x40490fdbu);
    const float pi_lo = __uint_as_float(0xb3bbbd2eu);
    const float pi_o_2 = __uint_as_float(0x3fc90fdbu);
    if (ix > 0x7f800000u || iy > 0x7f800000u) return __fadd_rn(x, y);
    if (hx == 0x3f800000u) return fdl_atanf(y);
    unsigned m = ((hy >> 31) & 1u) | ((hx >> 30) & 2u);
    if (iy == 0u) {
        switch (m) { case 0: case 1: return y; case 2: return pi; default: return -pi; }
    }
    if (ix == 0u) return (hy >> 31) ? -pi_o_2 : pi_o_2;
    if (ix == 0x7f800000u) {
        if (iy == 0x7f800000u) {
            float q = __fmul_rn(pi_o_2, 0.5f);
            switch (m) { case 0: return q; case 1: return -q;
                         case 2: return __fmul_rn(3.0f, q); default: return -__fmul_rn(3.0f, q); }
        } else {
            switch (m) { case 0: return 0.0f; case 1: return -0.0f;
                         case 2: return pi; default: return -pi; }
        }
    }
    if (iy == 0x7f800000u) return (hy >> 31) ? -pi_o_2 : pi_o_2;
    int k = ((int)iy - (int)ix) >> 23;
    float z;
    if (k > 26) {
        z = __fadd_rn(pi_o_2, __fmul_rn(0.5f, pi_lo));
        m &= 1u;
    } else if ((hx >> 31) && k < -26) {
        z = 0.0f;
    } else {
        z = fdl_atanf(fabsf(__fdiv_rn(y, x)));
    }
    switch (m) {
        case 0: return z;
        case 1: return -z;
        case 2: return __fsub_rn(pi, __fsub_rn(z, pi_lo));
        default: return __fsub_rn(__fsub_rn(z, pi_lo), pi);
    }
}

__device__ __forceinline__ int gidx_r(float v, float lo, float hi,
                                      float invcrop, float cells) {
    float c = fminf(fmaxf(v, lo), hi);
    float t = __fsub_rn(c, lo);
    float u = __fmul_rn(t, invcrop);
    float g = __fmul_rn(u, cells);
    return (int)floorf(g);
}

// init: zero bitmap + scan descriptors
#define INIT_BM (TOTW / 4)
__global__ __launch_bounds__(256) void k_init() {
    int i = blockIdx.x * blockDim.x + threadIdx.x;
    if (i < INIT_BM) {
        ((uint4*)g_bitmap)[i] = make_uint4(0, 0, 0, 0);
    } else if (i - INIT_BM < NBLK) {
        g_desc[i - INIT_BM] = 0ull;
    }
}

// points: compute bins, stage rows in smem, write coalesced full-sector runs
__global__ __launch_bounds__(256) void k_points(const float4* __restrict__ pts,
                                                const int* __restrict__ batch,
                                                float* __restrict__ out) {
    __shared__ float sbuf[3][1024];
    int blk = blockIdx.x, t = threadIdx.x;
    int i = blk * 256 + t;
    if (i < NPTS) {
        float4 p = pts[i];
        int b = batch[i];
        float r2 = __fadd_rn(__fmul_rn(p.x, p.x), __fmul_rn(p.y, p.y));
        float rho = __fsqrt_rn(r2);
        float phi = fdl_atan2f(p.y, p.x);
        const float PI = 3.14159265358979323846f;
        const float TWO_PI = __fadd_rn(PI, PI);
        const int D0[3] = {240, 120, 480};
        const int D1[3] = {180, 90, 360};
        const int D2[3] = {16, 8, 32};
        const float CX[3] = {239.f, 119.f, 479.f};
        const float CY[3] = {179.f, 89.f, 359.f};
        const float CZ[3] = {15.f, 7.f, 31.f};
        const int WF[3] = {WOFF0, WOFF1, WOFF2};
        const float INV_X = __fdiv_rn(1.0f, 50.0f);
        const float INV_Y = __fdiv_rn(1.0f, TWO_PI);
        const float INV_Z = __fdiv_rn(1.0f, 6.0f);
        float bf = (float)b;
#pragma unroll
        for (int s = 0; s < 3; s++) {
            int gx = gidx_r(rho, 0.f, 50.f, INV_X, CX[s]);
            int gy = gidx_r(phi, -PI, PI, INV_Y, CY[s]);
            int gz = gidx_r(p.z, -4.f, 2.f, INV_Z, CZ[s]);
            int key = ((b * D0[s] + gx) * D1[s] + gy) * D2[s] + gz;
            g_keys[s * NPTS + i] = key;
            atomicOr(&g_bitmap[WF[s] + (key >> 5)], 1u << (key & 31));
            sbuf[s][t * 4 + 0] = bf;
            sbuf[s][t * 4 + 1] = (float)gx;
            sbuf[s][t * 4 + 2] = (float)gy;
            sbuf[s][t * 4 + 3] = (float)gz;
        }
    }
    __syncthreads();
    long long ebase = (long long)blk * 1024;
#pragma unroll
    for (int s = 0; s < 3; s++) {
        float* base = out + (long long)s * OUTSTRIDE + ebase;
#pragma unroll
        for (int p = 0; p < 4; p++) {
            int el = p * 256 + t;
            if (ebase + el < 4ll * NPTS) base[el] = sbuf[s][el];
        }
    }
}

// single-pass scan with decoupled lookback (per-scale segments)
__global__ __launch_bounds__(256) void k_scan(float* __restrict__ out) {
    int t = threadIdx.x, blk = blockIdx.x;
    int lane = t & 31, warp = t >> 5;
    uint4 w = ((const uint4*)g_bitmap)[blk * 256 + t];
    int p0 = __popc(w.x), p1 = __popc(w.y), p2 = __popc(w.z), p3 = __popc(w.w);
    int ts = p0 + p1 + p2 + p3;
    int incl = ts;
    for (int o = 1; o < 32; o <<= 1) {
        int v = __shfl_up_sync(0xffffffffu, incl, o);
        if (lane >= o) incl += v;
    }
    __shared__ int ws[8], wb[8];
    __shared__ int sprefix;
    if (lane == 31) ws[warp] = incl;
    __syncthreads();
    if (t == 0) {
        int acc = 0;
#pragma unroll
        for (int k = 0; k < 8; k++) {
            wb[k] = acc;
            acc += ws[k];
        }
        int agg = acc;
        int segStart = (blk < SEG1) ? 0 : (blk < SEG2) ? SEG1 : SEG2;
        long long prefix = 0;
        volatile unsigned long long* desc = (volatile unsigned long long*)g_desc;
        if (blk == segStart) {
            desc[blk] = ((unsigned long long)agg << 2) | 2ull;  // inclusive ready
        } else {
            desc[blk] = ((unsigned long long)agg << 2) | 1ull;  // aggregate ready
            int j = blk - 1;
            for (;;) {
                unsigned long long d;
                do { d = desc[j]; } while ((d & 3ull) == 0ull);
                prefix += (long long)(d >> 2);
                if ((d & 3ull) == 2ull) break;
                j--;
            }
            desc[blk] = ((unsigned long long)(prefix + agg) << 2) | 2ull;
        }
        sprefix = (int)prefix;
        int segEnd = (blk < SEG1) ? SEG1 - 1 : (blk < SEG2) ? SEG2 - 1 : NBLK - 1;
        if (blk == segEnd) {
            int s = (blk < SEG1) ? 0 : (blk < SEG2) ? 1 : 2;
            int tot = (int)prefix + agg;
            g_num[s] = tot;
            out[(long long)s * OUTSTRIDE + 18000000] = (float)tot;
        }
    }
    __syncthreads();
    int ex = sprefix + wb[warp] + (incl - ts);
    uint4 o4;
    o4.x = ex;
    o4.y = ex + p0;
    o4.z = ex + p0 + p1;
    o4.w = ex + p0 + p1 + p2;
    ((uint4*)g_wpre)[blk * 256 + t] = o4;
}

template <int S>
__device__ __forceinline__ void scatter_words(int w, float* __restrict__ out) {
    constexpr int D0 = (S == 0) ? 240 : (S == 1) ? 120 : 480;
    constexpr int D1 = (S == 0) ? 180 : (S == 1) ? 90 : 360;
    constexpr int D2 = (S == 0) ? 16 : (S == 1) ? 8 : 32;
    constexpr int WOFF = (S == 0) ? WOFF0 : (S == 1) ? WOFF1 : WOFF2;
    unsigned word = g_bitmap[WOFF + w];
    if (!word) return;
    int rank = (int)g_wpre[WOFF + w];
    float* cb = out + (long long)S * OUTSTRIDE + 10000000;
    int keyBase = w << 5;
    while (word) {
        int bit = __ffs(word) - 1;
        word &= word - 1;
        int key = keyBase + bit;
        int z = key % D2;
        int t1 = key / D2;
        int y = t1 % D1;
        int t2 = t1 / D1;
        int x = t2 % D0;
        int b = t2 / D0;
        float* row = cb + 4ll * rank;
        row[0] = (float)b;
        row[1] = (float)z;
        row[2] = (float)y;
        row[3] = (float)x;
        rank++;
    }
}

// fused inv (4 el/thread) + scatter + ztail (16 el/thread)
__global__ __launch_bounds__(256) void k_invscat(float* __restrict__ out) {
    int blk = blockIdx.x, t = threadIdx.x;
    if (blk < NB_INV) {
        int base = blk * 1024 + t;
#pragma unroll
        for (int k = 0; k < 4; k++) {
            int idx = base + k * 256;
            if (idx < 3 * NPTS) {
                int s = idx / NPTS;
                int i = idx - s * NPTS;
                int key = g_keys[idx];
                int woff = (s == 0) ? WOFF0 : ((s == 1) ? WOFF1 : WOFF2);
                int w = woff + (key >> 5);
                int rank = (int)g_wpre[w] +
                           __popc(g_bitmap[w] & ((1u << (key & 31)) - 1u));
                out[(long long)s * OUTSTRIDE + 8000000 + i] = (float)rank;
            }
        }
        return;
    }
    int sb = blk - NB_INV;
    if (sb < NB_S0) { scatter_words<0>(sb * 256 + t, out); return; }
    sb -= NB_S0;
    if (sb < NB_S1) { scatter_words<1>(sb * 256 + t, out); return; }
    sb -= NB_S1;
    if (sb < NB_S2) { scatter_words<2>(sb * 256 + t, out); return; }
    sb -= NB_S2;
    int s = sb / NB_Z;
    int zb = sb - s * NB_Z;
    int lim = 4 * g_num[s];
    float* cb = out + (long long)s * OUTSTRIDE + 10000000;
    int base = zb * 4096 + t;
#pragma unroll
    for (int k = 0; k < 16; k++) {
        int idx = base + k * 256;
        if (idx < 8000000 && idx >= lim) cb[idx] = 0.0f;
    }
}

extern "C" void kernel_launch(void* const* d_in, const int* in_sizes, int n_in,
                              void* d_out, int out_size) {
    const float4* pts = (const float4*)d_in[0];
    const int* batch = (const int*)d_in[1];
    for (int i = 0; i < n_in; i++) {
        if (in_sizes[i] == 8000000) pts = (const float4*)d_in[i];
        else if (in_sizes[i] == 2000000) batch = (const int*)d_in[i];
    }
    float* out = (float*)d_out;

    k_init<<<(INIT_BM + NBLK + 255) / 256, 256>>>();
    k_points<<<(NPTS + 255) / 256, 256>>>(pts, batch, out);
    k_scan<<<NBLK, 256>>>(out);
    k_invscat<<<NB_INV + NB_S0 + NB_S1 + NB_S2 + 3 * NB_Z, 256>>>(out);
}